// round 11
// baseline (speedup 1.0000x reference)
#include <cuda_runtime.h>
#include <cstdint>

namespace {
constexpr int T_STEPS = 64;
constexpr int S_DIM = 16;
constexpr int B_DIM = 2048;
constexpr int SB = S_DIM * B_DIM;  // 32768 rows
constexpr int R = 64;              // rows per block
constexpr int NT = 128;
// dynamic smem (floats): Wf 4096 + zsw 4096 + eps 2*4096 + red 8
constexpr int SMEM_FLOATS = 4096 + 4096 + 2 * 4096 + 8;
constexpr int SMEM_BYTES = SMEM_FLOATS * 4;
}

__device__ float g_cd[B_DIM * 64];  // context @ Wc, [B][Z]

__global__ void ctx_kernel(const float* __restrict__ context,
                           const float* __restrict__ Wc) {
    int idx = blockIdx.x * blockDim.x + threadIdx.x;
    int b = idx >> 6, z = idx & 63;
    float acc = 0.f;
#pragma unroll
    for (int c = 0; c < 64; ++c)
        acc = fmaf(context[b * 64 + c], Wc[c * 64 + z], acc);
    g_cd[idx] = acc;
}

using u64 = unsigned long long;
__device__ __forceinline__ u64 pack2(float x, float y) {
    u64 r; asm("mov.b64 %0, {%1, %2};" : "=l"(r) : "f"(x), "f"(y)); return r;
}
__device__ __forceinline__ void unpack2(u64 v, float& x, float& y) {
    asm("mov.b64 {%0, %1}, %2;" : "=f"(x), "=f"(y) : "l"(v));
}
__device__ __forceinline__ void ffma2(u64& d, u64 a, u64 b) {
    asm("fma.rn.f32x2 %0, %1, %2, %0;" : "+l"(d) : "l"(a), "l"(b));
}
__device__ __forceinline__ u64 ffma2n(u64 a, u64 b, u64 c) {
    u64 d; asm("fma.rn.f32x2 %0, %1, %2, %3;" : "=l"(d) : "l"(a), "l"(b), "l"(c));
    return d;
}
__device__ __forceinline__ u64 add2(u64 a, u64 b) {
    u64 d; asm("add.rn.f32x2 %0, %1, %2;" : "=l"(d) : "l"(a), "l"(b)); return d;
}
__device__ __forceinline__ u64 mul2(u64 a, u64 b) {
    u64 d; asm("mul.rn.f32x2 %0, %1, %2;" : "=l"(d) : "l"(a), "l"(b)); return d;
}
__device__ __forceinline__ void mma_tf32(float* d, uint32_t a0, uint32_t a1,
                                         uint32_t a2, uint32_t a3,
                                         uint32_t b0, uint32_t b1) {
    asm("mma.sync.aligned.m16n8k8.row.col.f32.tf32.tf32.f32 "
        "{%0,%1,%2,%3}, {%4,%5,%6,%7}, {%8,%9}, {%0,%1,%2,%3};"
        : "+f"(d[0]), "+f"(d[1]), "+f"(d[2]), "+f"(d[3])
        : "r"(a0), "r"(a1), "r"(a2), "r"(a3), "r"(b0), "r"(b1));
}
__device__ __forceinline__ void cp16(uint32_t dst, const void* src) {
    asm volatile("cp.async.cg.shared.global [%0], [%1], 16;" :: "r"(dst), "l"(src));
}
// swizzled offset (floats) of (row r, col c) in a 64x64 tile: 16B-chunk rotate
__device__ __forceinline__ int zoff(int r, int c) {
    return r * 64 + ((c + 4 * (r & 7)) & 63);
}

__global__ void __launch_bounds__(NT, 4) scan_kernel(
    const float* __restrict__ z0, const float* __restrict__ eps,
    const float* __restrict__ W, const float* __restrict__ bvec,
    const float* __restrict__ sigmas, float* __restrict__ out) {
    extern __shared__ float smem[];
    u64* Wf = (u64*)smem;             // 2048 pre-packed B fragments
    float* zsw = smem + 4096;         // z tile, zoff-swizzled
    float* epsb = smem + 8192;        // 2 x [64][64] eps tiles, zoff-swizzled
    float* red = smem + 16384;

    const int tid = threadIdx.x;
    const int w = tid >> 5;
    const int l = tid & 31;
    const int a = l >> 2;
    const int b = l & 3;
    const int rA = w * 16 + a;
    const int rB = rA + 8;
    const int colb = 2 * b;
    const int r0 = blockIdx.x * R;
    const int b0i = r0 & (B_DIM - 1);
    const float dt = 1.0f / T_STEPS;
    const u64 dt2 = pack2(dt, dt);
    const uint32_t eps_u32 = (uint32_t)__cvta_generic_to_shared(epsb);

    // Wf: B-fragment (ks,nt,lane) = (W[8ks+b][8nt+a], W[8ks+b+4][8nt+a]) tf32
#pragma unroll
    for (int it = 0; it < 2048 / NT; ++it) {
        int idx = tid + it * NT;
        int ks = idx >> 8, nt = (idx >> 5) & 7, ll = idx & 31;
        int aa = ll >> 2, bb = ll & 3;
        float w0 = W[(8 * ks + bb) * 64 + 8 * nt + aa];
        float w1 = W[(8 * ks + bb + 4) * 64 + 8 * nt + aa];
        uint32_t t0, t1;
        asm("cvt.rna.tf32.f32 %0, %1;" : "=r"(t0) : "f"(w0));
        asm("cvt.rna.tf32.f32 %0, %1;" : "=r"(t1) : "f"(w1));
        Wf[idx] = ((u64)t1 << 32) | t0;
    }

    float* zs_out = out + 1;  // 4B-aligned only: scalar global stores
    u64 esq2 = 0, usq2 = 0;
    u64 up2[2][8], cd2[2][8];

    // init: z0 -> zsw + z0^2 ; ctx drift -> regs (const over t)
#pragma unroll
    for (int nt = 0; nt < 8; ++nt) {
#pragma unroll
        for (int h = 0; h < 2; ++h) {
            const int row = h ? rB : rA;
            u64 zz = *(const u64*)(z0 + (size_t)(r0 + row) * 64 + colb + 8 * nt);
            ffma2(esq2, zz, zz);
            up2[h][nt] = 0;
            *(u64*)(zsw + zoff(row, colb + 8 * nt)) = zz;
            cd2[h][nt] =
                *(const u64*)(g_cd + (size_t)(b0i + row) * 64 + colb + 8 * nt);
        }
    }

    // prefetch eps(0) into buffer 0 (warp-private rows)
    {
        const float* src0 = eps + (size_t)r0 * 64;
#pragma unroll
        for (int it = 0; it < 8; ++it) {
            int id = it * 32 + l;
            int rl = id >> 4, ch = id & 15;
            int row = w * 16 + rl;
            cp16(eps_u32 + (uint32_t)(row * 64 + 4 * ((ch + (row & 7)) & 15)) * 4u,
                 src0 + (size_t)row * 64 + ch * 4);
        }
        asm volatile("cp.async.commit_group;");
    }
    __syncthreads();  // Wf + zsw visible

    // z_samples[0]: coalesced store from zsw (LDS.64 pairs)
#pragma unroll
    for (int i = 0; i < 16; ++i) {
        const int row = w * 16 + i;
        size_t go = (size_t)(r0 + row) * 64;
        float x0, x1; unpack2(*(const u64*)(zsw + zoff(row, 2 * l)), x0, x1);
        __stcs(zs_out + go + 2 * l, x0);
        __stcs(zs_out + go + 2 * l + 1, x1);
    }

    const uint32_t* zswu = (const uint32_t*)zsw;
    u64 dtinvp2 = 0;

#pragma unroll 1
    for (int t = 0; t <= T_STEPS; ++t) {
        // prefetch eps(t+1)
        if (t + 1 < T_STEPS) {
            const float* src = eps + ((size_t)(t + 1) * SB + (size_t)r0) * 64;
            const uint32_t dst_u32 = eps_u32 + (uint32_t)(((t + 1) & 1) * 16384);
#pragma unroll
            for (int it = 0; it < 8; ++it) {
                int id = it * 32 + l;
                int rl = id >> 4, ch = id & 15;
                int row = w * 16 + rl;
                cp16(dst_u32 + (uint32_t)(row * 64 + 4 * ((ch + (row & 7)) & 15)) * 4u,
                     src + (size_t)row * 64 + ch * 4);
            }
            asm volatile("cp.async.commit_group;");
        }

        // ---- GEMM: drift = z_t @ W via HMMA ----
        float acc[8][4];
#pragma unroll
        for (int nt = 0; nt < 8; ++nt)
#pragma unroll
            for (int j = 0; j < 4; ++j) acc[nt][j] = 0.f;
#pragma unroll
        for (int ks = 0; ks < 8; ++ks) {
            uint32_t a0 = zswu[zoff(rA, 8 * ks + b)];
            uint32_t a2 = zswu[zoff(rA, 8 * ks + b + 4)];
            uint32_t a1 = zswu[zoff(rB, 8 * ks + b)];
            uint32_t a3 = zswu[zoff(rB, 8 * ks + b + 4)];
#pragma unroll
            for (int nt = 0; nt < 8; ++nt) {
                u64 bb = Wf[(ks * 8 + nt) * 32 + l];
                mma_tf32(acc[nt], a0, a1, a2, a3, (uint32_t)bb,
                         (uint32_t)(bb >> 32));
            }
        }

        if (t == T_STEPS) {  // final completion of u(T-1)
#pragma unroll
            for (int nt = 0; nt < 8; ++nt)
#pragma unroll
                for (int h = 0; h < 2; ++h) {
                    u64 d2 = pack2(acc[nt][2 * h], acc[nt][2 * h + 1]);
                    u64 u2 = ffma2n(d2, dtinvp2, up2[h][nt]);
                    ffma2(usq2, u2, u2);
                }
            break;
        }

        // eps(t) ready?
        if (t + 1 < T_STEPS) {
            asm volatile("cp.async.wait_group 1;" ::: "memory");
        } else {
            asm volatile("cp.async.wait_group 0;" ::: "memory");
        }
        __syncwarp();

        // ---- elementwise phase (frag layout; z_prev re-read from zsw) ----
        const float sig = __ldg(sigmas + t);
        const float stdv = sig * 0.125f;
        const float inv_std = 1.0f / stdv;
        const float dtinv = dt * inv_std;
        const u64 std2 = pack2(stdv, stdv);
        const u64 dtinv2 = pack2(dtinv, dtinv);
        const u64 ndtinv2 = pack2(-dtinv, -dtinv);
        const float* et = epsb + (t & 1) * 4096;
        const bool last = (t == T_STEPS - 1);

#pragma unroll
        for (int nt = 0; nt < 8; ++nt) {
            float2 btv = __ldg((const float2*)(bvec + t * 64 + colb + 8 * nt));
            u64 bt2 = pack2(btv.x, btv.y);
            u64 btd2 = mul2(bt2, dtinv2);
#pragma unroll
            for (int h = 0; h < 2; ++h) {
                const int row = h ? rB : rA;
                u64 d2 = pack2(acc[nt][2 * h], acc[nt][2 * h + 1]);
                u64 u2 = ffma2n(d2, dtinvp2, up2[h][nt]);  // complete u(t-1)
                ffma2(usq2, u2, u2);
                u64 zp2 = *(const u64*)(zsw + zoff(row, colb + 8 * nt));
                u64 e2 = *(const u64*)(et + zoff(row, colb + 8 * nt));
                u64 mu2 = add2(d2, add2(cd2[h][nt], bt2));
                u64 zn2 = ffma2n(e2, std2, ffma2n(mu2, dt2, zp2));
                up2[h][nt] =
                    ffma2n(mu2, ndtinv2, add2(e2 ^ 0x8000000080000000ull, btd2));
                ffma2(esq2, e2, e2);
                if (last) ffma2(usq2, zn2, zn2);
                *(u64*)(zsw + zoff(row, colb + 8 * nt)) = zn2;
            }
        }
        __syncwarp();  // zsw(t+1) visible within warp

        // ---- coalesced z_samples(t+1) stores from zsw ----
        float* zo = zs_out + (size_t)(t + 1) * SB * 64;
#pragma unroll
        for (int i = 0; i < 16; ++i) {
            const int row = w * 16 + i;
            size_t go = (size_t)(r0 + row) * 64;
            float x0, x1; unpack2(*(const u64*)(zsw + zoff(row, 2 * l)), x0, x1);
            __stcs(zo + go + 2 * l, x0);
            __stcs(zo + go + 2 * l + 1, x1);
        }
        dtinvp2 = dtinv2;
    }

    // reduce lw = (0.5/S) * (esq - usq)
    float e0, e1, q0, q1;
    unpack2(esq2, e0, e1);
    unpack2(usq2, q0, q1);
    float lw = (e0 + e1) - (q0 + q1);
#pragma unroll
    for (int off = 16; off; off >>= 1)
        lw += __shfl_down_sync(0xffffffffu, lw, off);
    if (l == 0) red[w] = lw;
    __syncthreads();
    if (tid == 0) {
        float s = red[0] + red[1] + red[2] + red[3];
        atomicAdd(out, (0.5f / S_DIM) * s);
    }
}

extern "C" void kernel_launch(void* const* d_in, const int* in_sizes, int n_in,
                              void* d_out, int out_size) {
    (void)in_sizes; (void)n_in; (void)out_size;
    const float* z0      = (const float*)d_in[0];
    const float* eps     = (const float*)d_in[1];
    const float* context = (const float*)d_in[2];
    const float* W       = (const float*)d_in[3];
    const float* Wc      = (const float*)d_in[4];
    const float* bvec    = (const float*)d_in[5];
    const float* sigmas  = (const float*)d_in[6];
    float* out = (float*)d_out;

    cudaFuncSetAttribute(scan_kernel,
                         cudaFuncAttributeMaxDynamicSharedMemorySize, SMEM_BYTES);
    cudaMemsetAsync(out, 0, sizeof(float));
    ctx_kernel<<<(B_DIM * 64) / 256, 256>>>(context, Wc);
    scan_kernel<<<SB / R, NT, SMEM_BYTES>>>(z0, eps, W, bvec, sigmas, out);
}

// round 12
// speedup vs baseline: 1.1002x; 1.1002x over previous
#include <cuda_runtime.h>
#include <cstdint>

namespace {
constexpr int T_STEPS = 64;
constexpr int S_DIM = 16;
constexpr int B_DIM = 2048;
constexpr int SB = S_DIM * B_DIM;  // 32768 rows
constexpr int R = 64;              // rows per block
constexpr int NT = 128;
// dynamic smem (floats): Wf 4096 + zsw 4096 + eps 2*4096 + red 8
constexpr int SMEM_FLOATS = 4096 + 4096 + 2 * 4096 + 8;
constexpr int SMEM_BYTES = SMEM_FLOATS * 4;
}

__device__ float g_cd[B_DIM * 64];  // context @ Wc, [B][Z]

__global__ void ctx_kernel(const float* __restrict__ context,
                           const float* __restrict__ Wc) {
    int idx = blockIdx.x * blockDim.x + threadIdx.x;
    int b = idx >> 6, z = idx & 63;
    float acc = 0.f;
#pragma unroll
    for (int c = 0; c < 64; ++c)
        acc = fmaf(context[b * 64 + c], Wc[c * 64 + z], acc);
    g_cd[idx] = acc;
}

using u64 = unsigned long long;
__device__ __forceinline__ u64 pack2(float x, float y) {
    u64 r; asm("mov.b64 %0, {%1, %2};" : "=l"(r) : "f"(x), "f"(y)); return r;
}
__device__ __forceinline__ void unpack2(u64 v, float& x, float& y) {
    asm("mov.b64 {%0, %1}, %2;" : "=f"(x), "=f"(y) : "l"(v));
}
__device__ __forceinline__ void ffma2(u64& d, u64 a, u64 b) {
    asm("fma.rn.f32x2 %0, %1, %2, %0;" : "+l"(d) : "l"(a), "l"(b));
}
__device__ __forceinline__ u64 ffma2n(u64 a, u64 b, u64 c) {
    u64 d; asm("fma.rn.f32x2 %0, %1, %2, %3;" : "=l"(d) : "l"(a), "l"(b), "l"(c));
    return d;
}
__device__ __forceinline__ u64 add2(u64 a, u64 b) {
    u64 d; asm("add.rn.f32x2 %0, %1, %2;" : "=l"(d) : "l"(a), "l"(b)); return d;
}
__device__ __forceinline__ u64 mul2(u64 a, u64 b) {
    u64 d; asm("mul.rn.f32x2 %0, %1, %2;" : "=l"(d) : "l"(a), "l"(b)); return d;
}
__device__ __forceinline__ void mma_tf32(float* d, uint32_t a0, uint32_t a1,
                                         uint32_t a2, uint32_t a3,
                                         uint32_t b0, uint32_t b1) {
    asm("mma.sync.aligned.m16n8k8.row.col.f32.tf32.tf32.f32 "
        "{%0,%1,%2,%3}, {%4,%5,%6,%7}, {%8,%9}, {%0,%1,%2,%3};"
        : "+f"(d[0]), "+f"(d[1]), "+f"(d[2]), "+f"(d[3])
        : "r"(a0), "r"(a1), "r"(a2), "r"(a3), "r"(b0), "r"(b1));
}
__device__ __forceinline__ void cp16(uint32_t dst, const void* src) {
    asm volatile("cp.async.cg.shared.global [%0], [%1], 16;" :: "r"(dst), "l"(src));
}
__device__ __forceinline__ void prefetch_l2(const void* p) {
    asm volatile("prefetch.global.L2 [%0];" :: "l"(p));
}
// swizzled offset (floats) of (row r, col c) in a 64x64 tile: 16B-chunk rotate
__device__ __forceinline__ int zoff(int r, int c) {
    return r * 64 + ((c + 4 * (r & 7)) & 63);
}

__global__ void __launch_bounds__(NT, 3) scan_kernel(
    const float* __restrict__ z0, const float* __restrict__ eps,
    const float* __restrict__ W, const float* __restrict__ bvec,
    const float* __restrict__ sigmas, float* __restrict__ out) {
    extern __shared__ float smem[];
    u64* Wf = (u64*)smem;             // 2048 pre-packed B fragments
    float* zsw = smem + 4096;         // z tile, zoff-swizzled
    float* epsb = smem + 8192;        // 2 x [64][64] eps tiles, zoff-swizzled
    float* red = smem + 16384;

    const int tid = threadIdx.x;
    const int w = tid >> 5;
    const int l = tid & 31;
    const int a = l >> 2;
    const int b = l & 3;
    const int rA = w * 16 + a;
    const int rB = rA + 8;
    const int colb = 2 * b;
    const int r0 = blockIdx.x * R;
    const int b0i = r0 & (B_DIM - 1);
    const float dt = 1.0f / T_STEPS;
    const u64 dt2 = pack2(dt, dt);
    const uint32_t eps_u32 = (uint32_t)__cvta_generic_to_shared(epsb);

    // Wf: B-fragment (ks,nt,lane) = (W[8ks+b][8nt+a], W[8ks+b+4][8nt+a]) tf32
#pragma unroll
    for (int it = 0; it < 2048 / NT; ++it) {
        int idx = tid + it * NT;
        int ks = idx >> 8, nt = (idx >> 5) & 7, ll = idx & 31;
        int aa = ll >> 2, bb = ll & 3;
        float w0 = W[(8 * ks + bb) * 64 + 8 * nt + aa];
        float w1 = W[(8 * ks + bb + 4) * 64 + 8 * nt + aa];
        uint32_t t0, t1;
        asm("cvt.rna.tf32.f32 %0, %1;" : "=r"(t0) : "f"(w0));
        asm("cvt.rna.tf32.f32 %0, %1;" : "=r"(t1) : "f"(w1));
        Wf[idx] = ((u64)t1 << 32) | t0;
    }

    float* zs_out = out + 1;  // 4B-aligned only: scalar global stores
    u64 esq2 = 0, usq2 = 0;
    u64 z2[2][8], up2[2][8], cd2[2][8];

    // init: z0 -> regs + zsw + z0^2 ; ctx drift -> regs (const over t)
#pragma unroll
    for (int nt = 0; nt < 8; ++nt) {
#pragma unroll
        for (int h = 0; h < 2; ++h) {
            const int row = h ? rB : rA;
            u64 zz = *(const u64*)(z0 + (size_t)(r0 + row) * 64 + colb + 8 * nt);
            ffma2(esq2, zz, zz);
            z2[h][nt] = zz;
            up2[h][nt] = 0;
            *(u64*)(zsw + zoff(row, colb + 8 * nt)) = zz;
            cd2[h][nt] =
                *(const u64*)(g_cd + (size_t)(b0i + row) * 64 + colb + 8 * nt);
        }
    }

    // warm L2 for eps(0) and eps(1): one 128B line per thread covers 16KB
    prefetch_l2((const char*)(eps + (size_t)r0 * 64) + tid * 128);
    prefetch_l2((const char*)(eps + ((size_t)SB + r0) * 64) + tid * 128);

    // prefetch eps(0) into buffer 0 (warp-private rows)
    {
        const float* src0 = eps + (size_t)r0 * 64;
#pragma unroll
        for (int it = 0; it < 8; ++it) {
            int id = it * 32 + l;
            int rl = id >> 4, ch = id & 15;
            int row = w * 16 + rl;
            cp16(eps_u32 + (uint32_t)(row * 64 + 4 * ((ch + (row & 7)) & 15)) * 4u,
                 src0 + (size_t)row * 64 + ch * 4);
        }
        asm volatile("cp.async.commit_group;");
    }
    __syncthreads();  // Wf + zsw visible

    // z_samples[0]: coalesced store from zsw
#pragma unroll
    for (int i = 0; i < 16; ++i) {
        const int row = w * 16 + i;
        size_t go = (size_t)(r0 + row) * 64;
        __stcs(zs_out + go + l, zsw[zoff(row, l)]);
        __stcs(zs_out + go + l + 32, zsw[zoff(row, l + 32)]);
    }

    const uint32_t* zswu = (const uint32_t*)zsw;
    u64 dtinvp2 = 0;

#pragma unroll 1
    for (int t = 0; t <= T_STEPS; ++t) {
        // L2 prefetch eps(t+2): fire-and-forget, deepens the DRAM pipeline
        if (t + 2 < T_STEPS) {
            const char* pf = (const char*)(eps + ((size_t)(t + 2) * SB + r0) * 64);
            prefetch_l2(pf + tid * 128);
        }
        // prefetch eps(t+1) smem (L2-hit after warmup)
        if (t + 1 < T_STEPS) {
            const float* src = eps + ((size_t)(t + 1) * SB + (size_t)r0) * 64;
            const uint32_t dst_u32 = eps_u32 + (uint32_t)(((t + 1) & 1) * 16384);
#pragma unroll
            for (int it = 0; it < 8; ++it) {
                int id = it * 32 + l;
                int rl = id >> 4, ch = id & 15;
                int row = w * 16 + rl;
                cp16(dst_u32 + (uint32_t)(row * 64 + 4 * ((ch + (row & 7)) & 15)) * 4u,
                     src + (size_t)row * 64 + ch * 4);
            }
            asm volatile("cp.async.commit_group;");
        }

        // ---- GEMM: drift = z_t @ W via HMMA ----
        float acc[8][4];
#pragma unroll
        for (int nt = 0; nt < 8; ++nt)
#pragma unroll
            for (int j = 0; j < 4; ++j) acc[nt][j] = 0.f;
#pragma unroll
        for (int ks = 0; ks < 8; ++ks) {
            uint32_t a0 = zswu[zoff(rA, 8 * ks + b)];
            uint32_t a2 = zswu[zoff(rA, 8 * ks + b + 4)];
            uint32_t a1 = zswu[zoff(rB, 8 * ks + b)];
            uint32_t a3 = zswu[zoff(rB, 8 * ks + b + 4)];
#pragma unroll
            for (int nt = 0; nt < 8; ++nt) {
                u64 bb = Wf[(ks * 8 + nt) * 32 + l];
                mma_tf32(acc[nt], a0, a1, a2, a3, (uint32_t)bb,
                         (uint32_t)(bb >> 32));
            }
        }

        if (t == T_STEPS) {  // final completion of u(T-1)
#pragma unroll
            for (int nt = 0; nt < 8; ++nt)
#pragma unroll
                for (int h = 0; h < 2; ++h) {
                    u64 d2 = pack2(acc[nt][2 * h], acc[nt][2 * h + 1]);
                    u64 u2 = ffma2n(d2, dtinvp2, up2[h][nt]);
                    ffma2(usq2, u2, u2);
                }
            break;
        }

        // eps(t) ready?
        if (t + 1 < T_STEPS) {
            asm volatile("cp.async.wait_group 1;" ::: "memory");
        } else {
            asm volatile("cp.async.wait_group 0;" ::: "memory");
        }
        __syncwarp();

        // ---- elementwise phase (frag layout) ----
        const float sig = __ldg(sigmas + t);
        const float stdv = sig * 0.125f;
        const float inv_std = 1.0f / stdv;
        const float dtinv = dt * inv_std;
        const u64 std2 = pack2(stdv, stdv);
        const u64 dtinv2 = pack2(dtinv, dtinv);
        const u64 ndtinv2 = pack2(-dtinv, -dtinv);
        const float* et = epsb + (t & 1) * 4096;
        const bool last = (t == T_STEPS - 1);

#pragma unroll
        for (int nt = 0; nt < 8; ++nt) {
            float2 btv = __ldg((const float2*)(bvec + t * 64 + colb + 8 * nt));
            u64 bt2 = pack2(btv.x, btv.y);
            u64 btd2 = mul2(bt2, dtinv2);
#pragma unroll
            for (int h = 0; h < 2; ++h) {
                const int row = h ? rB : rA;
                u64 d2 = pack2(acc[nt][2 * h], acc[nt][2 * h + 1]);
                u64 u2 = ffma2n(d2, dtinvp2, up2[h][nt]);  // complete u(t-1)
                ffma2(usq2, u2, u2);
                u64 e2 = *(const u64*)(et + zoff(row, colb + 8 * nt));
                u64 mu2 = add2(d2, add2(cd2[h][nt], bt2));
                u64 zn2 = ffma2n(e2, std2, ffma2n(mu2, dt2, z2[h][nt]));
                up2[h][nt] =
                    ffma2n(mu2, ndtinv2, add2(e2 ^ 0x8000000080000000ull, btd2));
                ffma2(esq2, e2, e2);
                if (last) ffma2(usq2, zn2, zn2);
                z2[h][nt] = zn2;
                *(u64*)(zsw + zoff(row, colb + 8 * nt)) = zn2;
            }
        }
        __syncwarp();  // zsw(t+1) visible within warp

        // ---- coalesced z_samples(t+1) stores from zsw ----
        float* zo = zs_out + (size_t)(t + 1) * SB * 64;
#pragma unroll
        for (int i = 0; i < 16; ++i) {
            const int row = w * 16 + i;
            size_t go = (size_t)(r0 + row) * 64;
            __stcs(zo + go + l, zsw[zoff(row, l)]);
            __stcs(zo + go + l + 32, zsw[zoff(row, l + 32)]);
        }
        dtinvp2 = dtinv2;
    }

    // reduce lw = (0.5/S) * (esq - usq)
    float e0, e1, q0, q1;
    unpack2(esq2, e0, e1);
    unpack2(usq2, q0, q1);
    float lw = (e0 + e1) - (q0 + q1);
#pragma unroll
    for (int off = 16; off; off >>= 1)
        lw += __shfl_down_sync(0xffffffffu, lw, off);
    if (l == 0) red[w] = lw;
    __syncthreads();
    if (tid == 0) {
        float s = red[0] + red[1] + red[2] + red[3];
        atomicAdd(out, (0.5f / S_DIM) * s);
    }
}

extern "C" void kernel_launch(void* const* d_in, const int* in_sizes, int n_in,
                              void* d_out, int out_size) {
    (void)in_sizes; (void)n_in; (void)out_size;
    const float* z0      = (const float*)d_in[0];
    const float* eps     = (const float*)d_in[1];
    const float* context = (const float*)d_in[2];
    const float* W       = (const float*)d_in[3];
    const float* Wc      = (const float*)d_in[4];
    const float* bvec    = (const float*)d_in[5];
    const float* sigmas  = (const float*)d_in[6];
    float* out = (float*)d_out;

    cudaFuncSetAttribute(scan_kernel,
                         cudaFuncAttributeMaxDynamicSharedMemorySize, SMEM_BYTES);
    cudaMemsetAsync(out, 0, sizeof(float));
    ctx_kernel<<<(B_DIM * 64) / 256, 256>>>(context, Wc);
    scan_kernel<<<SB / R, NT, SMEM_BYTES>>>(z0, eps, W, bvec, sigmas, out);
}

// round 13
// speedup vs baseline: 1.4020x; 1.2743x over previous
#include <cuda_runtime.h>
#include <cstdint>

namespace {
constexpr int T_STEPS = 64;
constexpr int S_DIM = 16;
constexpr int B_DIM = 2048;
constexpr int SB = S_DIM * B_DIM;  // 32768 rows
constexpr int R = 128;             // rows per block (2 chains/warp)
constexpr int NT = 128;
// dynamic smem (floats): Wf 4096 + zsw 8192 + eps 2*8192 + red 8
constexpr int SMEM_FLOATS = 4096 + 8192 + 2 * 8192 + 8;
constexpr int SMEM_BYTES = SMEM_FLOATS * 4;  // 114720 B
}

__device__ float g_cd[B_DIM * 64];  // context @ Wc, [B][Z]

__global__ void ctx_kernel(const float* __restrict__ context,
                           const float* __restrict__ Wc) {
    int idx = blockIdx.x * blockDim.x + threadIdx.x;
    int b = idx >> 6, z = idx & 63;
    float acc = 0.f;
#pragma unroll
    for (int c = 0; c < 64; ++c)
        acc = fmaf(context[b * 64 + c], Wc[c * 64 + z], acc);
    g_cd[idx] = acc;
}

using u64 = unsigned long long;
__device__ __forceinline__ u64 pack2(float x, float y) {
    u64 r; asm("mov.b64 %0, {%1, %2};" : "=l"(r) : "f"(x), "f"(y)); return r;
}
__device__ __forceinline__ void unpack2(u64 v, float& x, float& y) {
    asm("mov.b64 {%0, %1}, %2;" : "=f"(x), "=f"(y) : "l"(v));
}
__device__ __forceinline__ void ffma2(u64& d, u64 a, u64 b) {
    asm("fma.rn.f32x2 %0, %1, %2, %0;" : "+l"(d) : "l"(a), "l"(b));
}
__device__ __forceinline__ u64 ffma2n(u64 a, u64 b, u64 c) {
    u64 d; asm("fma.rn.f32x2 %0, %1, %2, %3;" : "=l"(d) : "l"(a), "l"(b), "l"(c));
    return d;
}
__device__ __forceinline__ u64 add2(u64 a, u64 b) {
    u64 d; asm("add.rn.f32x2 %0, %1, %2;" : "=l"(d) : "l"(a), "l"(b)); return d;
}
__device__ __forceinline__ u64 mul2(u64 a, u64 b) {
    u64 d; asm("mul.rn.f32x2 %0, %1, %2;" : "=l"(d) : "l"(a), "l"(b)); return d;
}
__device__ __forceinline__ void mma_tf32(float* d, uint32_t a0, uint32_t a1,
                                         uint32_t a2, uint32_t a3,
                                         uint32_t b0, uint32_t b1) {
    asm("mma.sync.aligned.m16n8k8.row.col.f32.tf32.tf32.f32 "
        "{%0,%1,%2,%3}, {%4,%5,%6,%7}, {%8,%9}, {%0,%1,%2,%3};"
        : "+f"(d[0]), "+f"(d[1]), "+f"(d[2]), "+f"(d[3])
        : "r"(a0), "r"(a1), "r"(a2), "r"(a3), "r"(b0), "r"(b1));
}
__device__ __forceinline__ void cp16(uint32_t dst, const void* src) {
    asm volatile("cp.async.cg.shared.global [%0], [%1], 16;" :: "r"(dst), "l"(src));
}
// swizzled offset (floats) of (row r, col c): 16B-chunk rotate per row
__device__ __forceinline__ int zoff(int r, int c) {
    return r * 64 + ((c + 4 * (r & 7)) & 63);
}

__global__ void __launch_bounds__(NT, 2) scan_kernel(
    const float* __restrict__ z0, const float* __restrict__ eps,
    const float* __restrict__ W, const float* __restrict__ bvec,
    const float* __restrict__ sigmas, float* __restrict__ out) {
    extern __shared__ float smem[];
    u64* Wf = (u64*)smem;             // 2048 pre-packed B fragments
    float* zsw = smem + 4096;         // z tile [128][64], zoff-swizzled
    float* epsb = smem + 12288;       // 2 x [128][64] eps tiles, zoff-swizzled
    float* red = smem + 28672;

    const int tid = threadIdx.x;
    const int w = tid >> 5;
    const int l = tid & 31;
    const int a = l >> 2;
    const int b = l & 3;
    const int colb = 2 * b;
    const int r0 = blockIdx.x * R;
    const int b0i = r0 & (B_DIM - 1);
    const float dt = 1.0f / T_STEPS;
    const u64 dt2 = pack2(dt, dt);
    const uint32_t eps_u32 = (uint32_t)__cvta_generic_to_shared(epsb);

    // Wf: B-fragment (ks,nt,lane) = (W[8ks+b][8nt+a], W[8ks+b+4][8nt+a]) tf32
#pragma unroll
    for (int it = 0; it < 2048 / NT; ++it) {
        int idx = tid + it * NT;
        int ks = idx >> 8, nt = (idx >> 5) & 7, ll = idx & 31;
        int aa = ll >> 2, bb = ll & 3;
        float w0 = W[(8 * ks + bb) * 64 + 8 * nt + aa];
        float w1 = W[(8 * ks + bb + 4) * 64 + 8 * nt + aa];
        uint32_t t0, t1;
        asm("cvt.rna.tf32.f32 %0, %1;" : "=r"(t0) : "f"(w0));
        asm("cvt.rna.tf32.f32 %0, %1;" : "=r"(t1) : "f"(w1));
        Wf[idx] = ((u64)t1 << 32) | t0;
    }

    float* zs_out = out + 1;  // 4B-aligned only: scalar global stores
    u64 esq2 = 0, usq2 = 0;
    u64 up2[2][2][8], cd2[2][2][8];  // [chain][h][nt]

    // init: z0 -> zsw + z0^2 ; ctx drift -> regs (const over t)
#pragma unroll
    for (int ti = 0; ti < 2; ++ti) {
        const int rA = ti * 64 + w * 16 + a;
#pragma unroll
        for (int nt = 0; nt < 8; ++nt) {
#pragma unroll
            for (int h = 0; h < 2; ++h) {
                const int row = rA + 8 * h;
                u64 zz = *(const u64*)(z0 + (size_t)(r0 + row) * 64 + colb + 8 * nt);
                ffma2(esq2, zz, zz);
                up2[ti][h][nt] = 0;
                *(u64*)(zsw + zoff(row, colb + 8 * nt)) = zz;
                cd2[ti][h][nt] =
                    *(const u64*)(g_cd + (size_t)(b0i + row) * 64 + colb + 8 * nt);
            }
        }
    }

    // prefetch eps(0) into buffer 0 (warp-private rows: both chains)
    {
        const float* src0 = eps + (size_t)r0 * 64;
#pragma unroll
        for (int it = 0; it < 16; ++it) {
            int id = it * 32 + l;
            int rl = id >> 4, ch = id & 15;
            int row = w * 16 + (rl & 15) + (rl >> 4) * 64;
            cp16(eps_u32 + (uint32_t)(row * 64 + 4 * ((ch + (row & 7)) & 15)) * 4u,
                 src0 + (size_t)row * 64 + ch * 4);
        }
        asm volatile("cp.async.commit_group;");
    }
    __syncthreads();  // Wf + zsw visible

    // z_samples[0]: coalesced store from zsw (32 rows/warp)
#pragma unroll
    for (int i = 0; i < 32; ++i) {
        const int row = w * 16 + (i & 15) + (i >> 4) * 64;
        size_t go = (size_t)(r0 + row) * 64;
        __stcs(zs_out + go + l, zsw[zoff(row, l)]);
        __stcs(zs_out + go + l + 32, zsw[zoff(row, l + 32)]);
    }

    const uint32_t* zswu = (const uint32_t*)zsw;
    u64 dtinvp2 = 0;

#pragma unroll 1
    for (int t = 0; t <= T_STEPS; ++t) {
        // prefetch eps(t+1)
        if (t + 1 < T_STEPS) {
            const float* src = eps + ((size_t)(t + 1) * SB + (size_t)r0) * 64;
            const uint32_t dst_u32 = eps_u32 + (uint32_t)(((t + 1) & 1) * 32768);
#pragma unroll
            for (int it = 0; it < 16; ++it) {
                int id = it * 32 + l;
                int rl = id >> 4, ch = id & 15;
                int row = w * 16 + (rl & 15) + (rl >> 4) * 64;
                cp16(dst_u32 + (uint32_t)(row * 64 + 4 * ((ch + (row & 7)) & 15)) * 4u,
                     src + (size_t)row * 64 + ch * 4);
            }
            asm volatile("cp.async.commit_group;");
        }

        // ---- GEMM x2 chains: drift = z_t @ W via HMMA ----
        float acc[2][8][4];
#pragma unroll
        for (int ti = 0; ti < 2; ++ti)
#pragma unroll
            for (int nt = 0; nt < 8; ++nt)
#pragma unroll
                for (int j = 0; j < 4; ++j) acc[ti][nt][j] = 0.f;
#pragma unroll
        for (int ks = 0; ks < 8; ++ks) {
#pragma unroll
            for (int ti = 0; ti < 2; ++ti) {
                const int rA = ti * 64 + w * 16 + a;
                const int rB = rA + 8;
                uint32_t a0 = zswu[zoff(rA, 8 * ks + b)];
                uint32_t a2 = zswu[zoff(rA, 8 * ks + b + 4)];
                uint32_t a1 = zswu[zoff(rB, 8 * ks + b)];
                uint32_t a3 = zswu[zoff(rB, 8 * ks + b + 4)];
#pragma unroll
                for (int nt = 0; nt < 8; ++nt) {
                    u64 bb = Wf[(ks * 8 + nt) * 32 + l];
                    mma_tf32(acc[ti][nt], a0, a1, a2, a3, (uint32_t)bb,
                             (uint32_t)(bb >> 32));
                }
            }
        }

        if (t == T_STEPS) {  // final completion of u(T-1), both chains
#pragma unroll
            for (int ti = 0; ti < 2; ++ti)
#pragma unroll
                for (int nt = 0; nt < 8; ++nt)
#pragma unroll
                    for (int h = 0; h < 2; ++h) {
                        u64 d2 = pack2(acc[ti][nt][2 * h], acc[ti][nt][2 * h + 1]);
                        u64 u2 = ffma2n(d2, dtinvp2, up2[ti][h][nt]);
                        ffma2(usq2, u2, u2);
                    }
            break;
        }

        // eps(t) ready?
        if (t + 1 < T_STEPS) {
            asm volatile("cp.async.wait_group 1;" ::: "memory");
        } else {
            asm volatile("cp.async.wait_group 0;" ::: "memory");
        }
        __syncwarp();

        // ---- elementwise phase (frag layout; z_prev re-read from zsw) ----
        const float sig = __ldg(sigmas + t);
        const float stdv = sig * 0.125f;
        const float inv_std = 1.0f / stdv;
        const float dtinv = dt * inv_std;
        const u64 std2 = pack2(stdv, stdv);
        const u64 dtinv2 = pack2(dtinv, dtinv);
        const u64 ndtinv2 = pack2(-dtinv, -dtinv);
        const float* et = epsb + (t & 1) * 8192;
        const bool last = (t == T_STEPS - 1);

#pragma unroll
        for (int nt = 0; nt < 8; ++nt) {
            float2 btv = __ldg((const float2*)(bvec + t * 64 + colb + 8 * nt));
            u64 bt2 = pack2(btv.x, btv.y);
            u64 btd2 = mul2(bt2, dtinv2);
#pragma unroll
            for (int ti = 0; ti < 2; ++ti) {
#pragma unroll
                for (int h = 0; h < 2; ++h) {
                    const int row = ti * 64 + w * 16 + a + 8 * h;
                    u64 d2 = pack2(acc[ti][nt][2 * h], acc[ti][nt][2 * h + 1]);
                    u64 u2 = ffma2n(d2, dtinvp2, up2[ti][h][nt]);  // u(t-1)
                    ffma2(usq2, u2, u2);
                    u64 zp2 = *(const u64*)(zsw + zoff(row, colb + 8 * nt));
                    u64 e2 = *(const u64*)(et + zoff(row, colb + 8 * nt));
                    u64 mu2 = add2(d2, add2(cd2[ti][h][nt], bt2));
                    u64 zn2 = ffma2n(e2, std2, ffma2n(mu2, dt2, zp2));
                    up2[ti][h][nt] = ffma2n(mu2, ndtinv2,
                                            add2(e2 ^ 0x8000000080000000ull, btd2));
                    ffma2(esq2, e2, e2);
                    if (last) ffma2(usq2, zn2, zn2);
                    *(u64*)(zsw + zoff(row, colb + 8 * nt)) = zn2;
                }
            }
        }
        __syncwarp();  // zsw(t+1) visible within warp

        // ---- coalesced z_samples(t+1) stores from zsw (32 rows/warp) ----
        float* zo = zs_out + (size_t)(t + 1) * SB * 64;
#pragma unroll
        for (int i = 0; i < 32; ++i) {
            const int row = w * 16 + (i & 15) + (i >> 4) * 64;
            size_t go = (size_t)(r0 + row) * 64;
            __stcs(zo + go + l, zsw[zoff(row, l)]);
            __stcs(zo + go + l + 32, zsw[zoff(row, l + 32)]);
        }
        dtinvp2 = dtinv2;
    }

    // reduce lw = (0.5/S) * (esq - usq)
    float e0, e1, q0, q1;
    unpack2(esq2, e0, e1);
    unpack2(usq2, q0, q1);
    float lw = (e0 + e1) - (q0 + q1);
#pragma unroll
    for (int off = 16; off; off >>= 1)
        lw += __shfl_down_sync(0xffffffffu, lw, off);
    if (l == 0) red[w] = lw;
    __syncthreads();
    if (tid == 0) {
        float s = red[0] + red[1] + red[2] + red[3];
        atomicAdd(out, (0.5f / S_DIM) * s);
    }
}

extern "C" void kernel_launch(void* const* d_in, const int* in_sizes, int n_in,
                              void* d_out, int out_size) {
    (void)in_sizes; (void)n_in; (void)out_size;
    const float* z0      = (const float*)d_in[0];
    const float* eps     = (const float*)d_in[1];
    const float* context = (const float*)d_in[2];
    const float* W       = (const float*)d_in[3];
    const float* Wc      = (const float*)d_in[4];
    const float* bvec    = (const float*)d_in[5];
    const float* sigmas  = (const float*)d_in[6];
    float* out = (float*)d_out;

    cudaFuncSetAttribute(scan_kernel,
                         cudaFuncAttributeMaxDynamicSharedMemorySize, SMEM_BYTES);
    cudaMemsetAsync(out, 0, sizeof(float));
    ctx_kernel<<<(B_DIM * 64) / 256, 256>>>(context, Wc);
    scan_kernel<<<SB / R, NT, SMEM_BYTES>>>(z0, eps, W, bvec, sigmas, out);
}

// round 14
// speedup vs baseline: 1.5625x; 1.1145x over previous
#include <cuda_runtime.h>
#include <cstdint>

namespace {
constexpr int T_STEPS = 64;
constexpr int S_DIM = 16;
constexpr int B_DIM = 2048;
constexpr int SB = S_DIM * B_DIM;  // 32768 rows
constexpr int R = 128;             // rows per block (1 chain/warp, 8 warps)
constexpr int NT = 256;
// dynamic smem (floats): Wf 4096 + zsw 8192 + eps 2*8192 + red 8
constexpr int SMEM_FLOATS = 4096 + 8192 + 2 * 8192 + 8;
constexpr int SMEM_BYTES = SMEM_FLOATS * 4;  // 114720 B
}

__device__ float g_cd[B_DIM * 64];  // context @ Wc, [B][Z]

__global__ void ctx_kernel(const float* __restrict__ context,
                           const float* __restrict__ Wc) {
    int idx = blockIdx.x * blockDim.x + threadIdx.x;
    int b = idx >> 6, z = idx & 63;
    float acc = 0.f;
#pragma unroll
    for (int c = 0; c < 64; ++c)
        acc = fmaf(context[b * 64 + c], Wc[c * 64 + z], acc);
    g_cd[idx] = acc;
}

using u64 = unsigned long long;
__device__ __forceinline__ u64 pack2(float x, float y) {
    u64 r; asm("mov.b64 %0, {%1, %2};" : "=l"(r) : "f"(x), "f"(y)); return r;
}
__device__ __forceinline__ void unpack2(u64 v, float& x, float& y) {
    asm("mov.b64 {%0, %1}, %2;" : "=f"(x), "=f"(y) : "l"(v));
}
__device__ __forceinline__ void ffma2(u64& d, u64 a, u64 b) {
    asm("fma.rn.f32x2 %0, %1, %2, %0;" : "+l"(d) : "l"(a), "l"(b));
}
__device__ __forceinline__ u64 ffma2n(u64 a, u64 b, u64 c) {
    u64 d; asm("fma.rn.f32x2 %0, %1, %2, %3;" : "=l"(d) : "l"(a), "l"(b), "l"(c));
    return d;
}
__device__ __forceinline__ u64 add2(u64 a, u64 b) {
    u64 d; asm("add.rn.f32x2 %0, %1, %2;" : "=l"(d) : "l"(a), "l"(b)); return d;
}
__device__ __forceinline__ u64 mul2(u64 a, u64 b) {
    u64 d; asm("mul.rn.f32x2 %0, %1, %2;" : "=l"(d) : "l"(a), "l"(b)); return d;
}
__device__ __forceinline__ void mma_tf32(float* d, uint32_t a0, uint32_t a1,
                                         uint32_t a2, uint32_t a3,
                                         uint32_t b0, uint32_t b1) {
    asm("mma.sync.aligned.m16n8k8.row.col.f32.tf32.tf32.f32 "
        "{%0,%1,%2,%3}, {%4,%5,%6,%7}, {%8,%9}, {%0,%1,%2,%3};"
        : "+f"(d[0]), "+f"(d[1]), "+f"(d[2]), "+f"(d[3])
        : "r"(a0), "r"(a1), "r"(a2), "r"(a3), "r"(b0), "r"(b1));
}
__device__ __forceinline__ void cp16(uint32_t dst, const void* src) {
    asm volatile("cp.async.cg.shared.global [%0], [%1], 16;" :: "r"(dst), "l"(src));
}
// swizzled offset (floats) of (row r, col c): 16B-chunk rotate per row
__device__ __forceinline__ int zoff(int r, int c) {
    return r * 64 + ((c + 4 * (r & 7)) & 63);
}

__global__ void __launch_bounds__(NT, 2) scan_kernel(
    const float* __restrict__ z0, const float* __restrict__ eps,
    const float* __restrict__ W, const float* __restrict__ bvec,
    const float* __restrict__ sigmas, float* __restrict__ out) {
    extern __shared__ float smem[];
    u64* Wf = (u64*)smem;             // 2048 pre-packed B fragments
    float* zsw = smem + 4096;         // z tile [128][64], zoff-swizzled
    float* epsb = smem + 12288;       // 2 x [128][64] eps tiles, zoff-swizzled
    float* red = smem + 28672;

    const int tid = threadIdx.x;
    const int w = tid >> 5;           // 8 warps, one 16-row chain each
    const int l = tid & 31;
    const int a = l >> 2;
    const int b = l & 3;
    const int colb = 2 * b;
    const int rA = w * 16 + a;
    const int rB = rA + 8;
    const int r0 = blockIdx.x * R;
    const int b0i = r0 & (B_DIM - 1);
    const float dt = 1.0f / T_STEPS;
    const u64 dt2 = pack2(dt, dt);
    const uint32_t eps_u32 = (uint32_t)__cvta_generic_to_shared(epsb);

    // Wf: B-fragment (ks,nt,lane) = (W[8ks+b][8nt+a], W[8ks+b+4][8nt+a]) tf32
#pragma unroll
    for (int it = 0; it < 2048 / NT; ++it) {
        int idx = tid + it * NT;
        int ks = idx >> 8, nt = (idx >> 5) & 7, ll = idx & 31;
        int aa = ll >> 2, bb = ll & 3;
        float w0 = W[(8 * ks + bb) * 64 + 8 * nt + aa];
        float w1 = W[(8 * ks + bb + 4) * 64 + 8 * nt + aa];
        uint32_t t0, t1;
        asm("cvt.rna.tf32.f32 %0, %1;" : "=r"(t0) : "f"(w0));
        asm("cvt.rna.tf32.f32 %0, %1;" : "=r"(t1) : "f"(w1));
        Wf[idx] = ((u64)t1 << 32) | t0;
    }

    float* zs_out = out + 1;  // 4B-aligned only: scalar global stores
    u64 esq2 = 0, usq2 = 0;
    u64 up2[2][8], cd2[2][8];  // [h][nt]

    // init: z0 -> zsw + z0^2 ; ctx drift -> regs (const over t)
#pragma unroll
    for (int nt = 0; nt < 8; ++nt) {
#pragma unroll
        for (int h = 0; h < 2; ++h) {
            const int row = h ? rB : rA;
            u64 zz = *(const u64*)(z0 + (size_t)(r0 + row) * 64 + colb + 8 * nt);
            ffma2(esq2, zz, zz);
            up2[h][nt] = 0;
            *(u64*)(zsw + zoff(row, colb + 8 * nt)) = zz;
            cd2[h][nt] =
                *(const u64*)(g_cd + (size_t)(b0i + row) * 64 + colb + 8 * nt);
        }
    }

    // prefetch eps(0) into buffer 0 (warp-private rows)
    {
        const float* src0 = eps + (size_t)r0 * 64;
#pragma unroll
        for (int it = 0; it < 8; ++it) {
            int id = it * 32 + l;
            int rl = id >> 4, ch = id & 15;
            int row = w * 16 + rl;
            cp16(eps_u32 + (uint32_t)(row * 64 + 4 * ((ch + (row & 7)) & 15)) * 4u,
                 src0 + (size_t)row * 64 + ch * 4);
        }
        asm volatile("cp.async.commit_group;");
    }
    __syncthreads();  // Wf + zsw visible

    // z_samples[0]: coalesced store from zsw (16 rows/warp)
#pragma unroll
    for (int i = 0; i < 16; ++i) {
        const int row = w * 16 + i;
        size_t go = (size_t)(r0 + row) * 64;
        __stcs(zs_out + go + l, zsw[zoff(row, l)]);
        __stcs(zs_out + go + l + 32, zsw[zoff(row, l + 32)]);
    }

    const uint32_t* zswu = (const uint32_t*)zsw;
    u64 dtinvp2 = 0;

#pragma unroll 1
    for (int t = 0; t <= T_STEPS; ++t) {
        // prefetch eps(t+1)
        if (t + 1 < T_STEPS) {
            const float* src = eps + ((size_t)(t + 1) * SB + (size_t)r0) * 64;
            const uint32_t dst_u32 = eps_u32 + (uint32_t)(((t + 1) & 1) * 32768);
#pragma unroll
            for (int it = 0; it < 8; ++it) {
                int id = it * 32 + l;
                int rl = id >> 4, ch = id & 15;
                int row = w * 16 + rl;
                cp16(dst_u32 + (uint32_t)(row * 64 + 4 * ((ch + (row & 7)) & 15)) * 4u,
                     src + (size_t)row * 64 + ch * 4);
            }
            asm volatile("cp.async.commit_group;");
        }

        // ---- GEMM: drift = z_t @ W via HMMA ----
        float acc[8][4];
#pragma unroll
        for (int nt = 0; nt < 8; ++nt)
#pragma unroll
            for (int j = 0; j < 4; ++j) acc[nt][j] = 0.f;
#pragma unroll
        for (int ks = 0; ks < 8; ++ks) {
            uint32_t a0 = zswu[zoff(rA, 8 * ks + b)];
            uint32_t a2 = zswu[zoff(rA, 8 * ks + b + 4)];
            uint32_t a1 = zswu[zoff(rB, 8 * ks + b)];
            uint32_t a3 = zswu[zoff(rB, 8 * ks + b + 4)];
#pragma unroll
            for (int nt = 0; nt < 8; ++nt) {
                u64 bb = Wf[(ks * 8 + nt) * 32 + l];
                mma_tf32(acc[nt], a0, a1, a2, a3, (uint32_t)bb,
                         (uint32_t)(bb >> 32));
            }
        }

        if (t == T_STEPS) {  // final completion of u(T-1)
#pragma unroll
            for (int nt = 0; nt < 8; ++nt)
#pragma unroll
                for (int h = 0; h < 2; ++h) {
                    u64 d2 = pack2(acc[nt][2 * h], acc[nt][2 * h + 1]);
                    u64 u2 = ffma2n(d2, dtinvp2, up2[h][nt]);
                    ffma2(usq2, u2, u2);
                }
            break;
        }

        // eps(t) ready?
        if (t + 1 < T_STEPS) {
            asm volatile("cp.async.wait_group 1;" ::: "memory");
        } else {
            asm volatile("cp.async.wait_group 0;" ::: "memory");
        }
        __syncwarp();

        // ---- elementwise phase (frag layout; z_prev re-read from zsw) ----
        const float sig = __ldg(sigmas + t);
        const float stdv = sig * 0.125f;
        const float inv_std = 1.0f / stdv;
        const float dtinv = dt * inv_std;
        const u64 std2 = pack2(stdv, stdv);
        const u64 dtinv2 = pack2(dtinv, dtinv);
        const u64 ndtinv2 = pack2(-dtinv, -dtinv);
        const float* et = epsb + (t & 1) * 8192;
        const bool last = (t == T_STEPS - 1);

#pragma unroll
        for (int nt = 0; nt < 8; ++nt) {
            float2 btv = __ldg((const float2*)(bvec + t * 64 + colb + 8 * nt));
            u64 bt2 = pack2(btv.x, btv.y);
            u64 btd2 = mul2(bt2, dtinv2);
#pragma unroll
            for (int h = 0; h < 2; ++h) {
                const int row = h ? rB : rA;
                u64 d2 = pack2(acc[nt][2 * h], acc[nt][2 * h + 1]);
                u64 u2 = ffma2n(d2, dtinvp2, up2[h][nt]);  // complete u(t-1)
                ffma2(usq2, u2, u2);
                u64 zp2 = *(const u64*)(zsw + zoff(row, colb + 8 * nt));
                u64 e2 = *(const u64*)(et + zoff(row, colb + 8 * nt));
                u64 mu2 = add2(d2, add2(cd2[h][nt], bt2));
                u64 zn2 = ffma2n(e2, std2, ffma2n(mu2, dt2, zp2));
                up2[h][nt] =
                    ffma2n(mu2, ndtinv2, add2(e2 ^ 0x8000000080000000ull, btd2));
                ffma2(esq2, e2, e2);
                if (last) ffma2(usq2, zn2, zn2);
                *(u64*)(zsw + zoff(row, colb + 8 * nt)) = zn2;
            }
        }
        __syncwarp();  // zsw(t+1) visible within warp

        // ---- coalesced z_samples(t+1) stores from zsw (16 rows/warp) ----
        float* zo = zs_out + (size_t)(t + 1) * SB * 64;
#pragma unroll
        for (int i = 0; i < 16; ++i) {
            const int row = w * 16 + i;
            size_t go = (size_t)(r0 + row) * 64;
            __stcs(zo + go + l, zsw[zoff(row, l)]);
            __stcs(zo + go + l + 32, zsw[zoff(row, l + 32)]);
        }
        dtinvp2 = dtinv2;
    }

    // reduce lw = (0.5/S) * (esq - usq)
    float e0, e1, q0, q1;
    unpack2(esq2, e0, e1);
    unpack2(usq2, q0, q1);
    float lw = (e0 + e1) - (q0 + q1);
#pragma unroll
    for (int off = 16; off; off >>= 1)
        lw += __shfl_down_sync(0xffffffffu, lw, off);
    if (l == 0) red[w] = lw;
    __syncthreads();
    if (tid == 0) {
        float s = 0.f;
#pragma unroll
        for (int i = 0; i < 8; ++i) s += red[i];
        atomicAdd(out, (0.5f / S_DIM) * s);
    }
}

extern "C" void kernel_launch(void* const* d_in, const int* in_sizes, int n_in,
                              void* d_out, int out_size) {
    (void)in_sizes; (void)n_in; (void)out_size;
    const float* z0      = (const float*)d_in[0];
    const float* eps     = (const float*)d_in[1];
    const float* context = (const float*)d_in[2];
    const float* W       = (const float*)d_in[3];
    const float* Wc      = (const float*)d_in[4];
    const float* bvec    = (const float*)d_in[5];
    const float* sigmas  = (const float*)d_in[6];
    float* out = (float*)d_out;

    cudaFuncSetAttribute(scan_kernel,
                         cudaFuncAttributeMaxDynamicSharedMemorySize, SMEM_BYTES);
    cudaMemsetAsync(out, 0, sizeof(float));
    ctx_kernel<<<(B_DIM * 64) / 256, 256>>>(context, Wc);
    scan_kernel<<<SB / R, NT, SMEM_BYTES>>>(z0, eps, W, bvec, sigmas, out);
}